// round 5
// baseline (speedup 1.0000x reference)
#include <cuda_runtime.h>
#include <cuda_fp16.h>
#include <cstdint>
#include <math.h>

#define TOK 32768
#define HDIM 1152
#define LHD 1152
#define HHD 4608
#define NCAT 5760          // LHD + HHD
#define BM 256
#define BN 128
#define BK 64
#define STAGES 4

// ---------------- device scratch (allocation-free rule) ----------------
__device__ __half g_xh[(size_t)TOK * HDIM];
__device__ __half g_cat[(size_t)TOK * NCAT];      // [p0*gelu(fc1l) | p1*gelu(fc1h)]
__device__ float  g_probs[TOK * 2];
__device__ __half g_w1cat[(size_t)NCAT * HDIM];   // [w1l ; w1h] row-concat
__device__ __half g_w2cat[(size_t)HDIM * NCAT];   // per-row k-concat [w2l | w2h]
__device__ float  g_b1cat[NCAT];

// ---------------- helpers ----------------
__device__ __forceinline__ float gelu_exact(float v) {
    return 0.5f * v * (1.0f + erff(v * 0.70710678118654752f));
}
__device__ __forceinline__ void cp_async16(uint32_t saddr, const void* gaddr) {
    asm volatile("cp.async.cg.shared.global [%0], [%1], 16;" :: "r"(saddr), "l"(gaddr));
}
__device__ __forceinline__ uint32_t smem_u32(const void* p) {
    uint32_t a;
    asm("{ .reg .u64 t; cvta.to.shared.u64 t, %1; cvt.u32.u64 %0, t; }" : "=r"(a) : "l"(p));
    return a;
}
#define SWZ(o) ((o) ^ (((o) >> 3) & 0x70))

__device__ __forceinline__ void ldsm_x4(uint32_t& r0, uint32_t& r1, uint32_t& r2, uint32_t& r3,
                                        uint32_t saddr) {
    asm volatile("ldmatrix.sync.aligned.m8n8.x4.shared.b16 {%0,%1,%2,%3}, [%4];"
                 : "=r"(r0), "=r"(r1), "=r"(r2), "=r"(r3) : "r"(saddr));
}
__device__ __forceinline__ void mma_f16(float* d, const uint32_t* a, uint32_t b0, uint32_t b1) {
    asm volatile(
        "mma.sync.aligned.m16n8k16.row.col.f32.f16.f16.f32 "
        "{%0,%1,%2,%3}, {%4,%5,%6,%7}, {%8,%9}, {%0,%1,%2,%3};"
        : "+f"(d[0]), "+f"(d[1]), "+f"(d[2]), "+f"(d[3])
        : "r"(a[0]), "r"(a[1]), "r"(a[2]), "r"(a[3]), "r"(b0), "r"(b1));
}

// ---------------------------------------------------------------------------
// Weight prep kernels
// ---------------------------------------------------------------------------
__global__ void cvt_lin_kernel(const float* __restrict__ in, __half* __restrict__ out, int n4) {
    int i = blockIdx.x * 256 + threadIdx.x;
    if (i < n4) {
        float4 v = ((const float4*)in)[i];
        ((__half2*)out)[i * 2 + 0] = __floats2half2_rn(v.x, v.y);
        ((__half2*)out)[i * 2 + 1] = __floats2half2_rn(v.z, v.w);
    }
}

__global__ void cvt_w2cat_kernel(const float* __restrict__ lw2, const float* __restrict__ hw2,
                                 __half* __restrict__ out) {
    int i = blockIdx.x * 256 + threadIdx.x;       // i over HDIM*NCAT/4
    if (i >= HDIM * NCAT / 4) return;
    int e = i * 4;
    int r = e / NCAT, k = e % NCAT;
    float4 v;
    if (k < LHD) v = *(const float4*)(lw2 + (size_t)r * LHD + k);
    else         v = *(const float4*)(hw2 + (size_t)r * HHD + (k - LHD));
    ((__half2*)out)[i * 2 + 0] = __floats2half2_rn(v.x, v.y);
    ((__half2*)out)[i * 2 + 1] = __floats2half2_rn(v.z, v.w);
}

__global__ void bcat_kernel(const float* __restrict__ lb1, const float* __restrict__ hb1,
                            float* __restrict__ out) {
    int i = blockIdx.x * 256 + threadIdx.x;
    if (i < NCAT) out[i] = (i < LHD) ? lb1[i] : hb1[i - LHD];
}

// ---------------------------------------------------------------------------
// Router (one warp per token) — also emits the fp16 copy of x.
// ---------------------------------------------------------------------------
__global__ void router_kernel(const float* __restrict__ x,
                              const float* __restrict__ rw,
                              const float* __restrict__ rb,
                              float* __restrict__ probs,
                              __half* __restrict__ xh) {
    int t = blockIdx.x * 8 + (threadIdx.x >> 5);
    int lane = threadIdx.x & 31;
    const float* xt = x + (size_t)t * HDIM;
    __half* xht = xh + (size_t)t * HDIM;
    float l0 = 0.f, l1 = 0.f;
    #pragma unroll 4
    for (int i = lane; i < HDIM; i += 32) {
        float v = xt[i];
        xht[i] = __float2half_rn(v);
        l0 += v * rw[i];
        l1 += v * rw[HDIM + i];
    }
    #pragma unroll
    for (int o = 16; o; o >>= 1) {
        l0 += __shfl_xor_sync(0xFFFFFFFFu, l0, o);
        l1 += __shfl_xor_sync(0xFFFFFFFFu, l1, o);
    }
    if (lane == 0) {
        l0 += rb[0];
        l1 += rb[1];
        float m = fmaxf(l0, l1);
        float e0 = expf(l0 - m), e1 = expf(l1 - m);
        float s = 1.0f / (e0 + e1);
        probs[t * 2 + 0] = e0 * s;
        probs[t * 2 + 1] = e1 * s;
    }
}

// ---------------------------------------------------------------------------
// fp16 GEMM, 256x128x64 tiles, warp tile 64x64, 4-stage cp.async, 1 sync/kt.
//   MODE 0 (fc1 fused): C(half) = p[row,expert(col)] * gelu(acc + b1cat[col])
//   MODE 1 (fc2 fused): C(float) = acc + p0[row]*lb2[col] + p1[row]*hb2[col]
// ---------------------------------------------------------------------------
template <int MODE>
__global__ void __launch_bounds__(256, 1)
gemm_big(const __half* __restrict__ A, const __half* __restrict__ B,
         const float* __restrict__ biasA, const float* __restrict__ biasB,
         const float* __restrict__ probs, void* __restrict__ Cv,
         int N, int K) {
    constexpr int ATILE = BM * BK * 2;       // 32768 B
    constexpr int BTILE = BN * BK * 2;       // 16384 B
    constexpr int STAGE = ATILE + BTILE;     // 49152 B
    extern __shared__ char smem_raw[];
    const uint32_t S0 = smem_u32(smem_raw);
    float* sBias = (float*)(smem_raw + STAGES * STAGE);

    const int tid = threadIdx.x;
    const int warp = tid >> 5;
    const int lane = tid & 31;
    const int g = lane >> 2, tg = lane & 3;
    const int wm = (warp >> 1) * 64;     // 4 warps along M
    const int wn = (warp & 1) * 64;      // 2 warps along N
    const int mBase = blockIdx.y * BM, nBase = blockIdx.x * BN;
    const int KT = K / BK;

    if (tid < BN) {
        sBias[tid] = biasA[nBase + tid];
        if (MODE == 1) sBias[BN + tid] = biasB[nBase + tid];
    }

    const __half* Ag = A + (size_t)mBase * K;
    const __half* Bg = B + (size_t)nBase * K;

    auto issue = [&](int kt) {
        const int s = kt & (STAGES - 1);
        const uint32_t stA = S0 + s * STAGE;
        const uint32_t stB = stA + ATILE;
        const int k0 = kt * BK;
        #pragma unroll
        for (int it = 0; it < 8; it++) {          // A: 256 rows x 128B
            int c = tid + it * 256;
            int row = c >> 3, col = c & 7;
            cp_async16(stA + SWZ(row * 128 + col * 16),
                       Ag + (size_t)row * K + k0 + col * 8);
        }
        #pragma unroll
        for (int it = 0; it < 4; it++) {          // B: 128 rows x 128B
            int c = tid + it * 256;
            int row = c >> 3, col = c & 7;
            cp_async16(stB + SWZ(row * 128 + col * 16),
                       Bg + (size_t)row * K + k0 + col * 8);
        }
        asm volatile("cp.async.commit_group;");
    };

    float acc[4][8][4];
    #pragma unroll
    for (int mi = 0; mi < 4; mi++)
        #pragma unroll
        for (int ni = 0; ni < 8; ni++)
            #pragma unroll
            for (int j = 0; j < 4; j++) acc[mi][ni][j] = 0.f;

    issue(0); issue(1); issue(2);

    const int lmr = lane & 15;
    const int lmk = (lane >> 4) * 16;

    for (int kt = 0; kt < KT; kt++) {
        if (kt < KT - 2)       asm volatile("cp.async.wait_group 2;");
        else if (kt == KT - 2) asm volatile("cp.async.wait_group 1;");
        else                   asm volatile("cp.async.wait_group 0;");
        __syncthreads();
        if (kt + 3 < KT) issue(kt + 3);

        const uint32_t stA = S0 + (kt & 3) * STAGE;
        const uint32_t stB = stA + ATILE;

        #pragma unroll
        for (int ks = 0; ks < 4; ks++) {
            const int kb = ks * 32;
            uint32_t af[4][4], bf[4][4];
            #pragma unroll
            for (int mi = 0; mi < 4; mi++)
                ldsm_x4(af[mi][0], af[mi][1], af[mi][2], af[mi][3],
                        stA + SWZ((wm + mi * 16 + lmr) * 128 + kb + lmk));
            #pragma unroll
            for (int np = 0; np < 4; np++)
                ldsm_x4(bf[np][0], bf[np][1], bf[np][2], bf[np][3],
                        stB + SWZ((wn + np * 16 + lmr) * 128 + kb + lmk));
            #pragma unroll
            for (int mi = 0; mi < 4; mi++) {
                #pragma unroll
                for (int np = 0; np < 4; np++) {
                    mma_f16(acc[mi][np * 2 + 0], af[mi], bf[np][0], bf[np][2]);
                    mma_f16(acc[mi][np * 2 + 1], af[mi], bf[np][1], bf[np][3]);
                }
            }
        }
    }

    // -------- epilogue --------
    if (MODE == 0) {
        const int pidx = (nBase >= LHD) ? 1 : 0;
        __half* Ch = (__half*)Cv;
        #pragma unroll
        for (int mi = 0; mi < 4; mi++) {
            int row = mBase + wm + mi * 16 + g;
            float pa = probs[row * 2 + pidx];
            float pb = probs[(row + 8) * 2 + pidx];
            #pragma unroll
            for (int ni = 0; ni < 8; ni++) {
                int col = wn + ni * 8 + tg * 2;
                float b0 = sBias[col], b1 = sBias[col + 1];
                float v00 = acc[mi][ni][0] + b0;
                float v01 = acc[mi][ni][1] + b1;
                float v10 = acc[mi][ni][2] + b0;
                float v11 = acc[mi][ni][3] + b1;
                *(__half2*)(Ch + (size_t)row * N + nBase + col) =
                    __floats2half2_rn(pa * gelu_exact(v00), pa * gelu_exact(v01));
                *(__half2*)(Ch + (size_t)(row + 8) * N + nBase + col) =
                    __floats2half2_rn(pb * gelu_exact(v10), pb * gelu_exact(v11));
            }
        }
    } else {
        float* Cf = (float*)Cv;
        #pragma unroll
        for (int mi = 0; mi < 4; mi++) {
            int row = mBase + wm + mi * 16 + g;
            float2 pr0 = ((const float2*)probs)[row];
            float2 pr1 = ((const float2*)probs)[row + 8];
            #pragma unroll
            for (int ni = 0; ni < 8; ni++) {
                int col = wn + ni * 8 + tg * 2;
                float bl0 = sBias[col], bl1 = sBias[col + 1];
                float bh0 = sBias[BN + col], bh1 = sBias[BN + col + 1];
                float2 o0, o1;
                o0.x = acc[mi][ni][0] + pr0.x * bl0 + pr0.y * bh0;
                o0.y = acc[mi][ni][1] + pr0.x * bl1 + pr0.y * bh1;
                o1.x = acc[mi][ni][2] + pr1.x * bl0 + pr1.y * bh0;
                o1.y = acc[mi][ni][3] + pr1.x * bl1 + pr1.y * bh1;
                *(float2*)(Cf + (size_t)row * N + nBase + col) = o0;
                *(float2*)(Cf + (size_t)(row + 8) * N + nBase + col) = o1;
            }
        }
    }
}

// ---------------------------------------------------------------------------
extern "C" void kernel_launch(void* const* d_in, const int* in_sizes, int n_in,
                              void* d_out, int out_size) {
    const float* x   = (const float*)d_in[0];
    const float* rw  = (const float*)d_in[1];
    const float* rb  = (const float*)d_in[2];
    const float* lw1 = (const float*)d_in[3];
    const float* lb1 = (const float*)d_in[4];
    const float* lw2 = (const float*)d_in[5];
    const float* lb2 = (const float*)d_in[6];
    const float* hw1 = (const float*)d_in[7];
    const float* hb1 = (const float*)d_in[8];
    const float* hw2 = (const float*)d_in[9];
    const float* hb2 = (const float*)d_in[10];
    float* out = (float*)d_out;

    __half *xh, *cat, *w1cat, *w2cat;
    float *probs, *b1cat;
    cudaGetSymbolAddress((void**)&xh, g_xh);
    cudaGetSymbolAddress((void**)&cat, g_cat);
    cudaGetSymbolAddress((void**)&probs, g_probs);
    cudaGetSymbolAddress((void**)&w1cat, g_w1cat);
    cudaGetSymbolAddress((void**)&w2cat, g_w2cat);
    cudaGetSymbolAddress((void**)&b1cat, g_b1cat);

    const int SMEM = STAGES * (BM + BN) * BK * 2 + 1024;  // 197632 B
    cudaFuncSetAttribute((const void*)gemm_big<0>, cudaFuncAttributeMaxDynamicSharedMemorySize, SMEM);
    cudaFuncSetAttribute((const void*)gemm_big<1>, cudaFuncAttributeMaxDynamicSharedMemorySize, SMEM);

    // weight/bias prep
    int n1 = LHD * HDIM / 4, n2 = HHD * HDIM / 4, n3 = HDIM * NCAT / 4;
    cvt_lin_kernel<<<(n1 + 255) / 256, 256>>>(lw1, w1cat, n1);
    cvt_lin_kernel<<<(n2 + 255) / 256, 256>>>(hw1, w1cat + (size_t)LHD * HDIM, n2);
    cvt_w2cat_kernel<<<(n3 + 255) / 256, 256>>>(lw2, hw2, w2cat);
    bcat_kernel<<<(NCAT + 255) / 256, 256>>>(lb1, hb1, b1cat);

    // router + fp16 x
    router_kernel<<<TOK / 8, 256>>>(x, rw, rb, probs, xh);

    // fc1 fused: cat = p[.,expert] * gelu(xh @ w1cat^T + b1cat)   [M=32768, N=5760, K=1152]
    gemm_big<0><<<dim3(NCAT / BN, TOK / BM), 256, SMEM>>>(
        xh, w1cat, b1cat, nullptr, probs, cat, NCAT, HDIM);
    // fc2 fused: out = cat @ w2cat^T + p0*lb2 + p1*hb2            [M=32768, N=1152, K=5760]
    gemm_big<1><<<dim3(HDIM / BN, TOK / BM), 256, SMEM>>>(
        cat, w2cat, lb2, hb2, probs, out, HDIM, NCAT);
}

// round 6
// speedup vs baseline: 1.0816x; 1.0816x over previous
#include <cuda_runtime.h>
#include <cuda_fp16.h>
#include <cstdint>
#include <math.h>

#define TOK 32768
#define HDIM 1152
#define LHD 1152
#define HHD 4608
#define NCAT 5760          // LHD + HHD
#define BM 128
#define BN 128
#define BK 64
#define STAGES 3

// ---------------- device scratch (allocation-free rule) ----------------
__device__ __half g_xh[(size_t)TOK * HDIM];
__device__ __half g_cat[(size_t)TOK * NCAT];      // [p0*gelu(fc1l) | p1*gelu(fc1h)]
__device__ float  g_probs[TOK * 2];
__device__ __half g_w1cat[(size_t)NCAT * HDIM];   // [w1l ; w1h] row-concat
__device__ __half g_w2cat[(size_t)HDIM * NCAT];   // per-row k-concat [w2l | w2h]
__device__ float  g_b1cat[NCAT];

// ---------------- helpers ----------------
__device__ __forceinline__ float gelu_exact(float v) {
    return 0.5f * v * (1.0f + erff(v * 0.70710678118654752f));
}
__device__ __forceinline__ void cp_async16(uint32_t saddr, const void* gaddr) {
    asm volatile("cp.async.cg.shared.global [%0], [%1], 16;" :: "r"(saddr), "l"(gaddr));
}
__device__ __forceinline__ uint32_t smem_u32(const void* p) {
    uint32_t a;
    asm("{ .reg .u64 t; cvta.to.shared.u64 t, %1; cvt.u32.u64 %0, t; }" : "=r"(a) : "l"(p));
    return a;
}
#define SWZ(o) ((o) ^ (((o) >> 3) & 0x70))

__device__ __forceinline__ void ldsm_x4(uint32_t& r0, uint32_t& r1, uint32_t& r2, uint32_t& r3,
                                        uint32_t saddr) {
    asm volatile("ldmatrix.sync.aligned.m8n8.x4.shared.b16 {%0,%1,%2,%3}, [%4];"
                 : "=r"(r0), "=r"(r1), "=r"(r2), "=r"(r3) : "r"(saddr));
}
__device__ __forceinline__ void mma_f16(float* d, const uint32_t* a, uint32_t b0, uint32_t b1) {
    asm volatile(
        "mma.sync.aligned.m16n8k16.row.col.f32.f16.f16.f32 "
        "{%0,%1,%2,%3}, {%4,%5,%6,%7}, {%8,%9}, {%0,%1,%2,%3};"
        : "+f"(d[0]), "+f"(d[1]), "+f"(d[2]), "+f"(d[3])
        : "r"(a[0]), "r"(a[1]), "r"(a[2]), "r"(a[3]), "r"(b0), "r"(b1));
}

// ---------------------------------------------------------------------------
// Weight prep kernels
// ---------------------------------------------------------------------------
__global__ void cvt_lin_kernel(const float* __restrict__ in, __half* __restrict__ out, int n4) {
    int i = blockIdx.x * 256 + threadIdx.x;
    if (i < n4) {
        float4 v = ((const float4*)in)[i];
        ((__half2*)out)[i * 2 + 0] = __floats2half2_rn(v.x, v.y);
        ((__half2*)out)[i * 2 + 1] = __floats2half2_rn(v.z, v.w);
    }
}

__global__ void cvt_w2cat_kernel(const float* __restrict__ lw2, const float* __restrict__ hw2,
                                 __half* __restrict__ out) {
    int i = blockIdx.x * 256 + threadIdx.x;       // i over HDIM*NCAT/4
    if (i >= HDIM * NCAT / 4) return;
    int e = i * 4;
    int r = e / NCAT, k = e % NCAT;
    float4 v;
    if (k < LHD) v = *(const float4*)(lw2 + (size_t)r * LHD + k);
    else         v = *(const float4*)(hw2 + (size_t)r * HHD + (k - LHD));
    ((__half2*)out)[i * 2 + 0] = __floats2half2_rn(v.x, v.y);
    ((__half2*)out)[i * 2 + 1] = __floats2half2_rn(v.z, v.w);
}

__global__ void bcat_kernel(const float* __restrict__ lb1, const float* __restrict__ hb1,
                            float* __restrict__ out) {
    int i = blockIdx.x * 256 + threadIdx.x;
    if (i < NCAT) out[i] = (i < LHD) ? lb1[i] : hb1[i - LHD];
}

// ---------------------------------------------------------------------------
// Router (one warp per token) — also emits the fp16 copy of x.
// ---------------------------------------------------------------------------
__global__ void router_kernel(const float* __restrict__ x,
                              const float* __restrict__ rw,
                              const float* __restrict__ rb,
                              float* __restrict__ probs,
                              __half* __restrict__ xh) {
    int t = blockIdx.x * 8 + (threadIdx.x >> 5);
    int lane = threadIdx.x & 31;
    const float* xt = x + (size_t)t * HDIM;
    __half* xht = xh + (size_t)t * HDIM;
    float l0 = 0.f, l1 = 0.f;
    #pragma unroll 4
    for (int i = lane; i < HDIM; i += 32) {
        float v = xt[i];
        xht[i] = __float2half_rn(v);
        l0 += v * rw[i];
        l1 += v * rw[HDIM + i];
    }
    #pragma unroll
    for (int o = 16; o; o >>= 1) {
        l0 += __shfl_xor_sync(0xFFFFFFFFu, l0, o);
        l1 += __shfl_xor_sync(0xFFFFFFFFu, l1, o);
    }
    if (lane == 0) {
        l0 += rb[0];
        l1 += rb[1];
        float m = fmaxf(l0, l1);
        float e0 = expf(l0 - m), e1 = expf(l1 - m);
        float s = 1.0f / (e0 + e1);
        probs[t * 2 + 0] = e0 * s;
        probs[t * 2 + 1] = e1 * s;
    }
}

// ---------------------------------------------------------------------------
// fp16 GEMM: 128x128x64 CTA, 4 warps (2x2), warp tile 64x64, 3-stage cp.async,
// single __syncthreads per K-tile, 2 CTAs/SM.
//   MODE 0 (fc1 fused): C(half) = p[row, expert(col)] * gelu(acc + b1cat[col])
//   MODE 1 (fc2 fused): C(float) = acc + p0[row]*lb2[col] + p1[row]*hb2[col]
// ---------------------------------------------------------------------------
template <int MODE>
__global__ void __launch_bounds__(128, 2)
gemm_f(const __half* __restrict__ A, const __half* __restrict__ B,
       const float* __restrict__ biasA, const float* __restrict__ biasB,
       const float* __restrict__ probs, void* __restrict__ Cv,
       int N, int K) {
    constexpr int TILE = BM * BK * 2;       // 16384 B per matrix
    constexpr int STAGE = 2 * TILE;         // 32768 B
    extern __shared__ char smem_raw[];
    const uint32_t S0 = smem_u32(smem_raw);
    float* sBias = (float*)(smem_raw + STAGES * STAGE);

    const int tid = threadIdx.x;
    const int warp = tid >> 5;
    const int lane = tid & 31;
    const int g = lane >> 2, tg = lane & 3;
    const int wm = (warp >> 1) * 64;     // 2 warps along M
    const int wn = (warp & 1) * 64;      // 2 warps along N
    const int mBase = blockIdx.y * BM, nBase = blockIdx.x * BN;
    const int KT = K / BK;

    if (tid < BN) {
        sBias[tid] = biasA[nBase + tid];
        if (MODE == 1) sBias[BN + tid] = biasB[nBase + tid];
    }

    const __half* Ag = A + (size_t)mBase * K;
    const __half* Bg = B + (size_t)nBase * K;

    auto issue = [&](int kt) {
        const int s = kt % STAGES;
        const uint32_t stA = S0 + s * STAGE;
        const uint32_t stB = stA + TILE;
        const int k0 = kt * BK;
        #pragma unroll
        for (int it = 0; it < 8; it++) {          // A: 128 rows x 128B = 1024 chunks
            int c = tid + it * 128;
            int row = c >> 3, col = c & 7;
            cp_async16(stA + SWZ(row * 128 + col * 16),
                       Ag + (size_t)row * K + k0 + col * 8);
        }
        #pragma unroll
        for (int it = 0; it < 8; it++) {          // B: 128 rows x 128B
            int c = tid + it * 128;
            int row = c >> 3, col = c & 7;
            cp_async16(stB + SWZ(row * 128 + col * 16),
                       Bg + (size_t)row * K + k0 + col * 8);
        }
        asm volatile("cp.async.commit_group;");
    };

    float acc[4][8][4];
    #pragma unroll
    for (int mi = 0; mi < 4; mi++)
        #pragma unroll
        for (int ni = 0; ni < 8; ni++)
            #pragma unroll
            for (int j = 0; j < 4; j++) acc[mi][ni][j] = 0.f;

    issue(0); issue(1);

    const int lmr = lane & 15;
    const int lmk = (lane >> 4) * 16;

    for (int kt = 0; kt < KT; kt++) {
        if (kt + 1 < KT) asm volatile("cp.async.wait_group 1;");
        else             asm volatile("cp.async.wait_group 0;");
        __syncthreads();
        if (kt + 2 < KT) issue(kt + 2);

        const uint32_t stA = S0 + (kt % STAGES) * STAGE;
        const uint32_t stB = stA + TILE;

        #pragma unroll
        for (int ks = 0; ks < 4; ks++) {
            const int kb = ks * 32;
            uint32_t af[4][4], bf[4][4];
            #pragma unroll
            for (int mi = 0; mi < 4; mi++)
                ldsm_x4(af[mi][0], af[mi][1], af[mi][2], af[mi][3],
                        stA + SWZ((wm + mi * 16 + lmr) * 128 + kb + lmk));
            #pragma unroll
            for (int np = 0; np < 4; np++)
                ldsm_x4(bf[np][0], bf[np][1], bf[np][2], bf[np][3],
                        stB + SWZ((wn + np * 16 + lmr) * 128 + kb + lmk));
            #pragma unroll
            for (int mi = 0; mi < 4; mi++) {
                #pragma unroll
                for (int np = 0; np < 4; np++) {
                    mma_f16(acc[mi][np * 2 + 0], af[mi], bf[np][0], bf[np][2]);
                    mma_f16(acc[mi][np * 2 + 1], af[mi], bf[np][1], bf[np][3]);
                }
            }
        }
    }

    // -------- epilogue --------
    if (MODE == 0) {
        const int pidx = (nBase >= LHD) ? 1 : 0;
        __half* Ch = (__half*)Cv;
        #pragma unroll
        for (int mi = 0; mi < 4; mi++) {
            int row = mBase + wm + mi * 16 + g;
            float pa = probs[row * 2 + pidx];
            float pb = probs[(row + 8) * 2 + pidx];
            #pragma unroll
            for (int ni = 0; ni < 8; ni++) {
                int col = wn + ni * 8 + tg * 2;
                float b0 = sBias[col], b1 = sBias[col + 1];
                float v00 = acc[mi][ni][0] + b0;
                float v01 = acc[mi][ni][1] + b1;
                float v10 = acc[mi][ni][2] + b0;
                float v11 = acc[mi][ni][3] + b1;
                *(__half2*)(Ch + (size_t)row * N + nBase + col) =
                    __floats2half2_rn(pa * gelu_exact(v00), pa * gelu_exact(v01));
                *(__half2*)(Ch + (size_t)(row + 8) * N + nBase + col) =
                    __floats2half2_rn(pb * gelu_exact(v10), pb * gelu_exact(v11));
            }
        }
    } else {
        float* Cf = (float*)Cv;
        #pragma unroll
        for (int mi = 0; mi < 4; mi++) {
            int row = mBase + wm + mi * 16 + g;
            float2 pr0 = ((const float2*)probs)[row];
            float2 pr1 = ((const float2*)probs)[row + 8];
            #pragma unroll
            for (int ni = 0; ni < 8; ni++) {
                int col = wn + ni * 8 + tg * 2;
                float bl0 = sBias[col], bl1 = sBias[col + 1];
                float bh0 = sBias[BN + col], bh1 = sBias[BN + col + 1];
                float2 o0, o1;
                o0.x = acc[mi][ni][0] + pr0.x * bl0 + pr0.y * bh0;
                o0.y = acc[mi][ni][1] + pr0.x * bl1 + pr0.y * bh1;
                o1.x = acc[mi][ni][2] + pr1.x * bl0 + pr1.y * bh0;
                o1.y = acc[mi][ni][3] + pr1.x * bl1 + pr1.y * bh1;
                *(float2*)(Cf + (size_t)row * N + nBase + col) = o0;
                *(float2*)(Cf + (size_t)(row + 8) * N + nBase + col) = o1;
            }
        }
    }
}

// ---------------------------------------------------------------------------
extern "C" void kernel_launch(void* const* d_in, const int* in_sizes, int n_in,
                              void* d_out, int out_size) {
    const float* x   = (const float*)d_in[0];
    const float* rw  = (const float*)d_in[1];
    const float* rb  = (const float*)d_in[2];
    const float* lw1 = (const float*)d_in[3];
    const float* lb1 = (const float*)d_in[4];
    const float* lw2 = (const float*)d_in[5];
    const float* lb2 = (const float*)d_in[6];
    const float* hw1 = (const float*)d_in[7];
    const float* hb1 = (const float*)d_in[8];
    const float* hw2 = (const float*)d_in[9];
    const float* hb2 = (const float*)d_in[10];
    float* out = (float*)d_out;

    __half *xh, *cat, *w1cat, *w2cat;
    float *probs, *b1cat;
    cudaGetSymbolAddress((void**)&xh, g_xh);
    cudaGetSymbolAddress((void**)&cat, g_cat);
    cudaGetSymbolAddress((void**)&probs, g_probs);
    cudaGetSymbolAddress((void**)&w1cat, g_w1cat);
    cudaGetSymbolAddress((void**)&w2cat, g_w2cat);
    cudaGetSymbolAddress((void**)&b1cat, g_b1cat);

    const int SMEM = STAGES * 2 * BM * BK * 2 + 1024;  // 99328 B
    cudaFuncSetAttribute((const void*)gemm_f<0>, cudaFuncAttributeMaxDynamicSharedMemorySize, SMEM);
    cudaFuncSetAttribute((const void*)gemm_f<1>, cudaFuncAttributeMaxDynamicSharedMemorySize, SMEM);

    // weight/bias prep
    int n1 = LHD * HDIM / 4, n2 = HHD * HDIM / 4, n3 = HDIM * NCAT / 4;
    cvt_lin_kernel<<<(n1 + 255) / 256, 256>>>(lw1, w1cat, n1);
    cvt_lin_kernel<<<(n2 + 255) / 256, 256>>>(hw1, w1cat + (size_t)LHD * HDIM, n2);
    cvt_w2cat_kernel<<<(n3 + 255) / 256, 256>>>(lw2, hw2, w2cat);
    bcat_kernel<<<(NCAT + 255) / 256, 256>>>(lb1, hb1, b1cat);

    // router + fp16 x
    router_kernel<<<TOK / 8, 256>>>(x, rw, rb, probs, xh);

    // fc1 fused: cat = p[.,expert] * gelu(xh @ w1cat^T + b1cat)   [M=32768, N=5760, K=1152]
    gemm_f<0><<<dim3(NCAT / BN, TOK / BM), 128, SMEM>>>(
        xh, w1cat, b1cat, nullptr, probs, cat, NCAT, HDIM);
    // fc2 fused: out = cat @ w2cat^T + p0*lb2 + p1*hb2            [M=32768, N=1152, K=5760]
    gemm_f<1><<<dim3(HDIM / BN, TOK / BM), 128, SMEM>>>(
        cat, w2cat, lb2, hb2, probs, out, HDIM, NCAT);
}

// round 8
// speedup vs baseline: 1.0855x; 1.0036x over previous
#include <cuda_runtime.h>
#include <cuda_fp16.h>
#include <cstdint>
#include <math.h>

#define TOK 32768
#define HDIM 1152
#define LHD 1152
#define HHD 4608
#define NCAT 5760          // LHD + HHD
#define BM 128
#define BN 128
#define BK 64
#define STAGES 3

// ---------------- device scratch (allocation-free rule) ----------------
__device__ __half g_xh[(size_t)TOK * HDIM];
__device__ __half g_cat[(size_t)TOK * NCAT];      // [p0*gelu(fc1l) | p1*gelu(fc1h)]
__device__ float  g_probs[TOK * 2];
__device__ __half g_w1cat[(size_t)NCAT * HDIM];   // [w1l ; w1h] row-concat
__device__ __half g_w2cat[(size_t)HDIM * NCAT];   // per-row k-concat [w2l | w2h]
__device__ float  g_b1cat[NCAT];

// ---------------- helpers ----------------
__device__ __forceinline__ float gelu_exact(float v) {
    return 0.5f * v * (1.0f + erff(v * 0.70710678118654752f));
}
__device__ __forceinline__ void cp_async16(uint32_t saddr, const void* gaddr) {
    asm volatile("cp.async.cg.shared.global [%0], [%1], 16;" :: "r"(saddr), "l"(gaddr));
}
__device__ __forceinline__ uint32_t smem_u32(const void* p) {
    uint32_t a;
    asm("{ .reg .u64 t; cvta.to.shared.u64 t, %1; cvt.u32.u64 %0, t; }" : "=r"(a) : "l"(p));
    return a;
}
#define SWZ(o) ((o) ^ (((o) >> 3) & 0x70))

__device__ __forceinline__ void ldsm_x4(uint32_t& r0, uint32_t& r1, uint32_t& r2, uint32_t& r3,
                                        uint32_t saddr) {
    asm volatile("ldmatrix.sync.aligned.m8n8.x4.shared.b16 {%0,%1,%2,%3}, [%4];"
                 : "=r"(r0), "=r"(r1), "=r"(r2), "=r"(r3) : "r"(saddr));
}
__device__ __forceinline__ void mma_f16(float* d, const uint32_t* a, uint32_t b0, uint32_t b1) {
    asm volatile(
        "mma.sync.aligned.m16n8k16.row.col.f32.f16.f16.f32 "
        "{%0,%1,%2,%3}, {%4,%5,%6,%7}, {%8,%9}, {%0,%1,%2,%3};"
        : "+f"(d[0]), "+f"(d[1]), "+f"(d[2]), "+f"(d[3])
        : "r"(a[0]), "r"(a[1]), "r"(a[2]), "r"(a[3]), "r"(b0), "r"(b1));
}

// ---------------------------------------------------------------------------
// Single fused weight/bias prep kernel (grid-stride over all regions).
// ---------------------------------------------------------------------------
__global__ void prep_kernel(const float* __restrict__ lw1, const float* __restrict__ hw1,
                            const float* __restrict__ lw2, const float* __restrict__ hw2,
                            const float* __restrict__ lb1, const float* __restrict__ hb1,
                            __half* __restrict__ w1cat, __half* __restrict__ w2cat,
                            float* __restrict__ b1cat) {
    const int n1 = LHD * HDIM / 4;          // lw1 -> w1cat
    const int n2 = HHD * HDIM / 4;          // hw1 -> w1cat + LHD*HDIM
    const int n3 = HDIM * NCAT / 4;         // [lw2|hw2] -> w2cat
    const int nb = NCAT / 4;                // bias concat
    const int total = n1 + n2 + n3 + nb;
    int i = blockIdx.x * 256 + threadIdx.x;
    if (i >= total) return;
    if (i < n1) {
        float4 v = ((const float4*)lw1)[i];
        ((__half2*)w1cat)[i * 2 + 0] = __floats2half2_rn(v.x, v.y);
        ((__half2*)w1cat)[i * 2 + 1] = __floats2half2_rn(v.z, v.w);
    } else if (i < n1 + n2) {
        int j = i - n1;
        float4 v = ((const float4*)hw1)[j];
        __half2* dst = (__half2*)(w1cat + (size_t)LHD * HDIM);
        dst[j * 2 + 0] = __floats2half2_rn(v.x, v.y);
        dst[j * 2 + 1] = __floats2half2_rn(v.z, v.w);
    } else if (i < n1 + n2 + n3) {
        int j = i - n1 - n2;
        int e = j * 4;
        int r = e / NCAT, k = e % NCAT;
        float4 v;
        if (k < LHD) v = *(const float4*)(lw2 + (size_t)r * LHD + k);
        else         v = *(const float4*)(hw2 + (size_t)r * HHD + (k - LHD));
        ((__half2*)w2cat)[j * 2 + 0] = __floats2half2_rn(v.x, v.y);
        ((__half2*)w2cat)[j * 2 + 1] = __floats2half2_rn(v.z, v.w);
    } else {
        int j = (i - n1 - n2 - n3) * 4;
        #pragma unroll
        for (int q = 0; q < 4; q++) {
            int k = j + q;
            b1cat[k] = (k < LHD) ? lb1[k] : hb1[k - LHD];
        }
    }
}

// ---------------------------------------------------------------------------
// Router (one warp per token) — also emits the fp16 copy of x.
// ---------------------------------------------------------------------------
__global__ void router_kernel(const float* __restrict__ x,
                              const float* __restrict__ rw,
                              const float* __restrict__ rb,
                              float* __restrict__ probs,
                              __half* __restrict__ xh) {
    int t = blockIdx.x * 8 + (threadIdx.x >> 5);
    int lane = threadIdx.x & 31;
    const float* xt = x + (size_t)t * HDIM;
    __half* xht = xh + (size_t)t * HDIM;
    float l0 = 0.f, l1 = 0.f;
    #pragma unroll 4
    for (int i = lane; i < HDIM; i += 32) {
        float v = xt[i];
        xht[i] = __float2half_rn(v);
        l0 += v * rw[i];
        l1 += v * rw[HDIM + i];
    }
    #pragma unroll
    for (int o = 16; o; o >>= 1) {
        l0 += __shfl_xor_sync(0xFFFFFFFFu, l0, o);
        l1 += __shfl_xor_sync(0xFFFFFFFFu, l1, o);
    }
    if (lane == 0) {
        l0 += rb[0];
        l1 += rb[1];
        float m = fmaxf(l0, l1);
        float e0 = expf(l0 - m), e1 = expf(l1 - m);
        float s = 1.0f / (e0 + e1);
        probs[t * 2 + 0] = e0 * s;
        probs[t * 2 + 1] = e1 * s;
    }
}

// ---------------------------------------------------------------------------
// fp16 GEMM: 128x128x64 CTA, 4 warps (2x2), warp tile 64x64, 3-stage cp.async,
// single __syncthreads per K-tile, 2 CTAs/SM, fragment double-buffering.
//   MODE 0 (fc1 fused): C(half) = p[row, expert(col)] * gelu(acc + b1cat[col])
//   MODE 1 (fc2 fused): C(float) = acc + p0[row]*lb2[col] + p1[row]*hb2[col]
// ---------------------------------------------------------------------------
template <int MODE>
__global__ void __launch_bounds__(128, 2)
gemm_f(const __half* __restrict__ A, const __half* __restrict__ B,
       const float* __restrict__ biasA, const float* __restrict__ biasB,
       const float* __restrict__ probs, void* __restrict__ Cv,
       int N, int K) {
    constexpr int TILE = BM * BK * 2;       // 16384 B per matrix
    constexpr int STAGE = 2 * TILE;         // 32768 B
    extern __shared__ char smem_raw[];
    const uint32_t S0 = smem_u32(smem_raw);
    float* sBias = (float*)(smem_raw + STAGES * STAGE);

    const int tid = threadIdx.x;
    const int warp = tid >> 5;
    const int lane = tid & 31;
    const int g = lane >> 2, tg = lane & 3;
    const int wm = (warp >> 1) * 64;     // 2 warps along M
    const int wn = (warp & 1) * 64;      // 2 warps along N
    const int mBase = blockIdx.y * BM, nBase = blockIdx.x * BN;
    const int KT = K / BK;

    if (tid < BN) {
        sBias[tid] = biasA[nBase + tid];
        if (MODE == 1) sBias[BN + tid] = biasB[nBase + tid];
    }

    const __half* Ag = A + (size_t)mBase * K;
    const __half* Bg = B + (size_t)nBase * K;

    auto issue = [&](int kt) {
        const int s = kt % STAGES;
        const uint32_t stA = S0 + s * STAGE;
        const uint32_t stB = stA + TILE;
        const int k0 = kt * BK;
        #pragma unroll
        for (int it = 0; it < 8; it++) {          // A: 128 rows x 128B
            int c = tid + it * 128;
            int row = c >> 3, col = c & 7;
            cp_async16(stA + SWZ(row * 128 + col * 16),
                       Ag + (size_t)row * K + k0 + col * 8);
        }
        #pragma unroll
        for (int it = 0; it < 8; it++) {          // B: 128 rows x 128B
            int c = tid + it * 128;
            int row = c >> 3, col = c & 7;
            cp_async16(stB + SWZ(row * 128 + col * 16),
                       Bg + (size_t)row * K + k0 + col * 8);
        }
        asm volatile("cp.async.commit_group;");
    };

    float acc[4][8][4];
    #pragma unroll
    for (int mi = 0; mi < 4; mi++)
        #pragma unroll
        for (int ni = 0; ni < 8; ni++)
            #pragma unroll
            for (int j = 0; j < 4; j++) acc[mi][ni][j] = 0.f;

    issue(0); issue(1);

    const int lmr = lane & 15;
    const int lmk = (lane >> 4) * 16;

    uint32_t af[2][4][4], bf[2][4][4];

    auto load_frags = [&](uint32_t stA, uint32_t stB, int ks, int buf) {
        const int kb = ks * 32;
        #pragma unroll
        for (int mi = 0; mi < 4; mi++)
            ldsm_x4(af[buf][mi][0], af[buf][mi][1], af[buf][mi][2], af[buf][mi][3],
                    stA + SWZ((wm + mi * 16 + lmr) * 128 + kb + lmk));
        #pragma unroll
        for (int np = 0; np < 4; np++)
            ldsm_x4(bf[buf][np][0], bf[buf][np][1], bf[buf][np][2], bf[buf][np][3],
                    stB + SWZ((wn + np * 16 + lmr) * 128 + kb + lmk));
    };

    for (int kt = 0; kt < KT; kt++) {
        if (kt + 1 < KT) asm volatile("cp.async.wait_group 1;");
        else             asm volatile("cp.async.wait_group 0;");
        __syncthreads();
        if (kt + 2 < KT) issue(kt + 2);

        const uint32_t stA = S0 + (kt % STAGES) * STAGE;
        const uint32_t stB = stA + TILE;

        load_frags(stA, stB, 0, 0);
        #pragma unroll
        for (int ks = 0; ks < 4; ks++) {
            const int cur = ks & 1;
            if (ks < 3) load_frags(stA, stB, ks + 1, cur ^ 1);
            #pragma unroll
            for (int mi = 0; mi < 4; mi++) {
                #pragma unroll
                for (int np = 0; np < 4; np++) {
                    mma_f16(acc[mi][np * 2 + 0], af[cur][mi], bf[cur][np][0], bf[cur][np][2]);
                    mma_f16(acc[mi][np * 2 + 1], af[cur][mi], bf[cur][np][1], bf[cur][np][3]);
                }
            }
        }
    }

    // -------- epilogue --------
    if (MODE == 0) {
        const int pidx = (nBase >= LHD) ? 1 : 0;
        __half* Ch = (__half*)Cv;
        #pragma unroll
        for (int mi = 0; mi < 4; mi++) {
            int row = mBase + wm + mi * 16 + g;
            float pa = probs[row * 2 + pidx];
            float pb = probs[(row + 8) * 2 + pidx];
            #pragma unroll
            for (int ni = 0; ni < 8; ni++) {
                int col = wn + ni * 8 + tg * 2;
                float b0 = sBias[col], b1 = sBias[col + 1];
                float v00 = acc[mi][ni][0] + b0;
                float v01 = acc[mi][ni][1] + b1;
                float v10 = acc[mi][ni][2] + b0;
                float v11 = acc[mi][ni][3] + b1;
                *(__half2*)(Ch + (size_t)row * N + nBase + col) =
                    __floats2half2_rn(pa * gelu_exact(v00), pa * gelu_exact(v01));
                *(__half2*)(Ch + (size_t)(row + 8) * N + nBase + col) =
                    __floats2half2_rn(pb * gelu_exact(v10), pb * gelu_exact(v11));
            }
        }
    } else {
        float* Cf = (float*)Cv;
        #pragma unroll
        for (int mi = 0; mi < 4; mi++) {
            int row = mBase + wm + mi * 16 + g;
            float2 pr0 = ((const float2*)probs)[row];
            float2 pr1 = ((const float2*)probs)[row + 8];
            #pragma unroll
            for (int ni = 0; ni < 8; ni++) {
                int col = wn + ni * 8 + tg * 2;
                float bl0 = sBias[col], bl1 = sBias[col + 1];
                float bh0 = sBias[BN + col], bh1 = sBias[BN + col + 1];
                float2 o0, o1;
                o0.x = acc[mi][ni][0] + pr0.x * bl0 + pr0.y * bh0;
                o0.y = acc[mi][ni][1] + pr0.x * bl1 + pr0.y * bh1;
                o1.x = acc[mi][ni][2] + pr1.x * bl0 + pr1.y * bh0;
                o1.y = acc[mi][ni][3] + pr1.x * bl1 + pr1.y * bh1;
                *(float2*)(Cf + (size_t)row * N + nBase + col) = o0;
                *(float2*)(Cf + (size_t)(row + 8) * N + nBase + col) = o1;
            }
        }
    }
}

// ---------------------------------------------------------------------------
extern "C" void kernel_launch(void* const* d_in, const int* in_sizes, int n_in,
                              void* d_out, int out_size) {
    const float* x   = (const float*)d_in[0];
    const float* rw  = (const float*)d_in[1];
    const float* rb  = (const float*)d_in[2];
    const float* lw1 = (const float*)d_in[3];
    const float* lb1 = (const float*)d_in[4];
    const float* lw2 = (const float*)d_in[5];
    const float* lb2 = (const float*)d_in[6];
    const float* hw1 = (const float*)d_in[7];
    const float* hb1 = (const float*)d_in[8];
    const float* hw2 = (const float*)d_in[9];
    const float* hb2 = (const float*)d_in[10];
    float* out = (float*)d_out;

    __half *xh, *cat, *w1cat, *w2cat;
    float *probs, *b1cat;
    cudaGetSymbolAddress((void**)&xh, g_xh);
    cudaGetSymbolAddress((void**)&cat, g_cat);
    cudaGetSymbolAddress((void**)&probs, g_probs);
    cudaGetSymbolAddress((void**)&w1cat, g_w1cat);
    cudaGetSymbolAddress((void**)&w2cat, g_w2cat);
    cudaGetSymbolAddress((void**)&b1cat, g_b1cat);

    const int SMEM = STAGES * 2 * BM * BK * 2 + 1024;  // 99328 B
    cudaFuncSetAttribute((const void*)gemm_f<0>, cudaFuncAttributeMaxDynamicSharedMemorySize, SMEM);
    cudaFuncSetAttribute((const void*)gemm_f<1>, cudaFuncAttributeMaxDynamicSharedMemorySize, SMEM);

    // fused weight/bias prep (one launch)
    const int n1 = LHD * HDIM / 4, n2 = HHD * HDIM / 4, n3 = HDIM * NCAT / 4, nb = NCAT / 4;
    const int total = n1 + n2 + n3 + nb;
    prep_kernel<<<(total + 255) / 256, 256>>>(lw1, hw1, lw2, hw2, lb1, hb1, w1cat, w2cat, b1cat);

    // router + fp16 x
    router_kernel<<<TOK / 8, 256>>>(x, rw, rb, probs, xh);

    // fc1 fused: cat = p[.,expert] * gelu(xh @ w1cat^T + b1cat)   [M=32768, N=5760, K=1152]
    gemm_f<0><<<dim3(NCAT / BN, TOK / BM), 128, SMEM>>>(
        xh, w1cat, b1cat, nullptr, probs, cat, NCAT, HDIM);
    // fc2 fused: out = cat @ w2cat^T + p0*lb2 + p1*hb2            [M=32768, N=1152, K=5760]
    gemm_f<1><<<dim3(HDIM / BN, TOK / BM), 128, SMEM>>>(
        cat, w2cat, lb2, hb2, probs, out, HDIM, NCAT);
}